// round 16
// baseline (speedup 1.0000x reference)
#include <cuda_runtime.h>

// SSIM, fused single-pass box filters, 4 cols/lane, aligned float4 loads,
// DUAL independent row-streams per warp at FULL grid width.
//
// img (16,3,512,512) f32; channel 0, crop 4 -> 504x504.
// Groups: ext base e0 = 116g-8 (16B-aligned quads/lane); 118 windows/warp,
// per-element ov ranges partition [0,504). Vertical 11-row running sums;
// horizontal 11-window via win4 (5 shfl -> 4 outputs).
// 72 strips of 7 rows; each warp owns strips (s, s+36): two independent
// chains interleaved for 2x intra-warp ILP. 5 groups x 16 img x 36 pairs =
// 2880 warps -> 720 blocks x 128 (same distribution as the best config).

#define IMG_STRIDE (3 * 512 * 512)
#define W4 128            // float4 per image row (512 floats)
#define OUTW 504
#define NGROUPS 5
#define STRIP_H 7         // 72*7 = 504
#define SPAIR 36          // pairs (s, s+36)
#define NWARPS (NGROUPS * 16 * SPAIR)       // 2880
#define WPB 4
#define NBLOCKS (NWARPS / WPB)              // 720
#define RETIRE_OFF (11 * W4)                // retire row = admit row - 11

__device__ float g_partials[NBLOCKS];
__device__ int   g_count = 0;

__device__ __forceinline__ float rcp_approx(float x) {
    float r; asm("rcp.approx.f32 %0, %1;" : "=f"(r) : "f"(x)); return r;
}

// Horizontal 11-window: lane L holds ext elems m=4L..4L+3 (v0..v3).
// W[k] = sum over ext m'=4L+k .. m'+10.
__device__ __forceinline__ void win4(float v0, float v1, float v2, float v3,
                                     float& W0, float& W1, float& W2, float& W3)
{
    const unsigned m = 0xffffffffu;
    const float p2 = v0 + v1;
    const float p3 = p2 + v2;
    const float T  = p3 + v3;
    const float suf1 = T - v0;
    const float suf2 = v2 + v3;
    const float Tn1  = __shfl_down_sync(m, T,  1);
    const float Tn2  = __shfl_down_sync(m, T,  2);
    const float p3n2 = __shfl_down_sync(m, p3, 2);
    const float p1n3 = __shfl_down_sync(m, v0, 3);
    const float p2n3 = __shfl_down_sync(m, p2, 3);
    const float TT = Tn1 + Tn2;
    W0 = T + Tn1 + p3n2;
    W1 = suf1 + TT;
    W2 = (suf2 + p1n3) + TT;
    W3 = (v3 + p2n3) + TT;
}

#define ADMIT(V1, V2, Vss, V12, k, av, bv)                   \
    V1[k] += (av); V2[k] += (bv);                            \
    Vss[k] = fmaf((av), (av), Vss[k]);                       \
    Vss[k] = fmaf((bv), (bv), Vss[k]);                       \
    V12[k] = fmaf((av), (bv), V12[k]);

#define UPDATE(V1, V2, Vss, V12, k, an, bn, ao, bo)          \
    V1[k] += (an) - (ao); V2[k] += (bn) - (bo);              \
    Vss[k] = fmaf((an), (an), Vss[k]);                       \
    Vss[k] = fmaf((bn), (bn), Vss[k]);                       \
    Vss[k] = fmaf(-(ao), (ao), Vss[k]);                      \
    Vss[k] = fmaf(-(bo), (bo), Vss[k]);                      \
    V12[k] = fmaf((an), (bn), V12[k]);                       \
    V12[k] = fmaf(-(ao), (bo), V12[k]);

// win4 x4 + SSIM + acc for one stream's current state.
#define SSIM_ROW(V1, V2, Vss, V12, ACC)                                   \
    {                                                                     \
        float B1[4], B2[4], Bs[4], Bc[4];                                 \
        win4(V1[0],V1[1],V1[2],V1[3],   B1[0],B1[1],B1[2],B1[3]);         \
        win4(V2[0],V2[1],V2[2],V2[3],   B2[0],B2[1],B2[2],B2[3]);         \
        win4(Vss[0],Vss[1],Vss[2],Vss[3],Bs[0],Bs[1],Bs[2],Bs[3]);        \
        win4(V12[0],V12[1],V12[2],V12[3],Bc[0],Bc[1],Bc[2],Bc[3]);        \
        float nm[4], dn[4];                                               \
        _Pragma("unroll")                                                 \
        for (int k = 0; k < 4; ++k) {                                     \
            const float P   = B1[k] * B2[k];                              \
            const float Q   = fmaf(B1[k], B1[k], B2[k] * B2[k]);          \
            const float t12 = fmaf(121.f, Bc[k], -P);                     \
            const float tss = fmaf(121.f, Bs[k], -Q);                     \
            nm[k] = fmaf(2.f, P, C1K) * fmaf(2.f, t12, C2K);              \
            dn[k] = (Q + C1K) * (tss + C2K);                              \
        }                                                                 \
        _Pragma("unroll")                                                 \
        for (int p = 0; p < 2; ++p) {                                     \
            const int k0 = 2*p, k1 = 2*p+1;                               \
            const float rr = rcp_approx(dn[k0] * dn[k1]);                 \
            const float t0 = nm[k0] * dn[k1];                             \
            const float t1 = nm[k1] * dn[k0];                             \
            if (ov[k0]) ACC = fmaf(t0, rr, ACC);                          \
            if (ov[k1]) ACC = fmaf(t1, rr, ACC);                          \
        }                                                                 \
    }

__global__ __launch_bounds__(128) void ssim_main(
    const float* __restrict__ img1, const float* __restrict__ img2,
    float* __restrict__ out)
{
    const int wib  = threadIdx.x >> 5;
    const int w    = blockIdx.x * WPB + wib;
    const int lane = threadIdx.x & 31;
    const int tid  = threadIdx.x;

    const int g    = w % NGROUPS;
    const int t    = w / NGROUPS;
    const int img  = t & 15;
    const int sp   = t >> 4;                 // 0..35

    // Aligned ext base; output range partition over groups.
    const int e0 = 116 * g - 8;
    const int lo = (g == 0) ? 0    : (116 * g - 3);
    const int hi = (g == 4) ? OUTW : (116 * g + 113);

    const int ec = e0 + 4 * lane;                  // lane's quad ext start
    const bool loadok = (ec >= 0) && (ec <= 500);  // whole quad in [0,504)

    bool ov[4];
    #pragma unroll
    for (int k = 0; k < 4; ++k) {
        const int c = ec + 5 + k;                  // output col of W[k]
        ov[k] = (c >= lo) && (c < hi);
    }

    // Quad pointers: global col = ec + 4 (aligned); row r at +(r+4)*W4.
    const float4* q1 = reinterpret_cast<const float4*>(
        img1 + (size_t)img * IMG_STRIDE) + ((ec >> 2) + 1);
    const float4* q2 = reinterpret_cast<const float4*>(
        img2 + (size_t)img * IMG_STRIDE) + ((ec >> 2) + 1);

    const int r0A = sp * STRIP_H;                  // 0..245
    const int r0B = (sp + SPAIR) * STRIP_H;        // 252..497 (always >= 5)

    float V1A[4]={0,0,0,0}, V2A[4]={0,0,0,0}, VsA[4]={0,0,0,0}, VcA[4]={0,0,0,0};
    float V1B[4]={0,0,0,0}, V2B[4]={0,0,0,0}, VsB[4]={0,0,0,0}, VcB[4]={0,0,0,0};

    // Prologue: V = rows r0-5 .. r0+5 for both streams (zero-pad below 0).
    {
        const float4* a1 = q1 + (ptrdiff_t)(r0A - 1) * W4;   // row r0A-5
        const float4* a2 = q2 + (ptrdiff_t)(r0A - 1) * W4;
        const float4* b1 = q1 + (ptrdiff_t)(r0B - 1) * W4;   // row r0B-5
        const float4* b2 = q2 + (ptrdiff_t)(r0B - 1) * W4;
        #pragma unroll
        for (int j = 0; j < 11; ++j) {
            const int rA = r0A - 5 + j;
            float4 xa = {0,0,0,0}, xb = {0,0,0,0};
            float4 ya = {0,0,0,0}, yb = {0,0,0,0};
            if (loadok && rA >= 0) { xa = __ldg(a1); xb = __ldg(a2); }
            if (loadok)            { ya = __ldg(b1); yb = __ldg(b2); }
            a1 += W4; a2 += W4; b1 += W4; b2 += W4;
            ADMIT(V1A,V2A,VsA,VcA, 0, xa.x, xb.x)
            ADMIT(V1A,V2A,VsA,VcA, 1, xa.y, xb.y)
            ADMIT(V1A,V2A,VsA,VcA, 2, xa.z, xb.z)
            ADMIT(V1A,V2A,VsA,VcA, 3, xa.w, xb.w)
            ADMIT(V1B,V2B,VsB,VcB, 0, ya.x, yb.x)
            ADMIT(V1B,V2B,VsB,VcB, 1, ya.y, yb.y)
            ADMIT(V1B,V2B,VsB,VcB, 2, ya.z, yb.z)
            ADMIT(V1B,V2B,VsB,VcB, 3, ya.w, yb.w)
        }
    }

    const float C1K = 6.5025f  * 14641.f;   // C1 * 121^2
    const float C2K = 58.5225f * 14641.f;   // C2 * 121^2
    float accA = 0.f, accB = 0.f;

    const float4* pA1 = q1 + (ptrdiff_t)(r0A + 10) * W4;  // admit row r0A+6
    const float4* pA2 = q2 + (ptrdiff_t)(r0A + 10) * W4;
    const float4* pB1 = q1 + (ptrdiff_t)(r0B + 10) * W4;  // admit row r0B+6
    const float4* pB2 = q2 + (ptrdiff_t)(r0B + 10) * W4;

    #pragma unroll 1
    for (int i = 0; i < STRIP_H; ++i) {
        const int yA = r0A + i;
        const int yB = r0B + i;

        // All loads for both streams first (max MLP; consumed much later).
        float4 naA={0,0,0,0}, nbA={0,0,0,0}, oaA={0,0,0,0}, obA={0,0,0,0};
        float4 naB={0,0,0,0}, nbB={0,0,0,0}, oaB={0,0,0,0}, obB={0,0,0,0};
        if (loadok && yA <= OUTW - 7) { naA = __ldg(pA1); nbA = __ldg(pA2); }
        if (loadok && yA >= 5) {
            oaA = __ldg(pA1 - RETIRE_OFF); obA = __ldg(pA2 - RETIRE_OFF);
        }
        if (loadok && yB <= OUTW - 7) { naB = __ldg(pB1); nbB = __ldg(pB2); }
        if (loadok) {                                  // yB >= 252 always
            oaB = __ldg(pB1 - RETIRE_OFF); obB = __ldg(pB2 - RETIRE_OFF);
        }
        pA1 += W4; pA2 += W4; pB1 += W4; pB2 += W4;

        // Two independent window+SSIM chains (interleaved by scheduler).
        SSIM_ROW(V1A, V2A, VsA, VcA, accA)
        SSIM_ROW(V1B, V2B, VsB, VcB, accB)

        UPDATE(V1A,V2A,VsA,VcA, 0, naA.x, nbA.x, oaA.x, obA.x)
        UPDATE(V1B,V2B,VsB,VcB, 0, naB.x, nbB.x, oaB.x, obB.x)
        UPDATE(V1A,V2A,VsA,VcA, 1, naA.y, nbA.y, oaA.y, obA.y)
        UPDATE(V1B,V2B,VsB,VcB, 1, naB.y, nbB.y, oaB.y, obB.y)
        UPDATE(V1A,V2A,VsA,VcA, 2, naA.z, nbA.z, oaA.z, obA.z)
        UPDATE(V1B,V2B,VsB,VcB, 2, naB.z, nbB.z, oaB.z, obB.z)
        UPDATE(V1A,V2A,VsA,VcA, 3, naA.w, nbA.w, oaA.w, obA.w)
        UPDATE(V1B,V2B,VsB,VcB, 3, naB.w, nbB.w, oaB.w, obB.w)
    }

    // ---- block partial + fused final reduction ----
    float acc = accA + accB;
    #pragma unroll
    for (int d = 16; d; d >>= 1)
        acc += __shfl_xor_sync(0xffffffffu, acc, d);

    __shared__ float sp_[WPB];
    __shared__ int   isLast;
    if (lane == 0) sp_[wib] = acc;
    __syncthreads();
    if (tid == 0) {
        g_partials[blockIdx.x] = sp_[0] + sp_[1] + sp_[2] + sp_[3];
        __threadfence();
        isLast = (atomicAdd(&g_count, 1) == NBLOCKS - 1);
    }
    __syncthreads();

    if (isLast) {
        float v = 0.f;
        for (int i = tid; i < NBLOCKS; i += 128)
            v += __ldcg(&g_partials[i]);
        #pragma unroll
        for (int d = 16; d; d >>= 1)
            v += __shfl_xor_sync(0xffffffffu, v, d);
        if (lane == 0) sp_[wib] = v;
        __syncthreads();
        if (tid == 0) {
            out[0] = (sp_[0] + sp_[1] + sp_[2] + sp_[3]) * (1.0f / 4064256.0f);
            g_count = 0;   // reset for next graph replay
        }
    }
}

extern "C" void kernel_launch(void* const* d_in, const int* in_sizes, int n_in,
                              void* d_out, int out_size)
{
    const float* img1 = (const float*)d_in[0];
    const float* img2 = (const float*)d_in[1];
    float* out = (float*)d_out;
    ssim_main<<<NBLOCKS, 128>>>(img1, img2, out);
}

// round 17
// speedup vs baseline: 1.4662x; 1.4662x over previous
#include <cuda_runtime.h>

// SSIM, fused single-pass box filters, 4 cols/lane, aligned float4 loads,
// software-prefetched vertical updates, paired reciprocals, WAVE-EXACT grid.
//
// img (16,3,512,512) f32; channel 0, crop 4 -> 504x504.
// Groups: ext base e0 = 116g-8 (16B-aligned quads/lane); 118 windows/warp,
// per-element ov ranges partition [0,504). Vertical 11-row running sums;
// horizontal 11-window via win4 (5 shfl -> 4 outputs).
// 37 strips per (group,image): 23 of 14 rows + 14 of 13 rows (= 504).
// 5 groups x 16 img x 37 strips = 2960 warps -> 740 blocks = 5 x 148 SMs:
// every SM runs exactly 5 CTAs -> no partial-wave tail (vs 720 = W/144).

#define IMG_STRIDE (3 * 512 * 512)
#define W4 128            // float4 per image row (512 floats)
#define OUTW 504
#define NGROUPS 5
#define NSTRIPS 37
#define NWARPS (NGROUPS * 16 * NSTRIPS)     // 2960
#define WPB 4
#define NBLOCKS (NWARPS / WPB)              // 740
#define RETIRE_OFF (11 * W4)                // retire row = admit row - 11

__device__ float g_partials[NBLOCKS];
__device__ int   g_count = 0;

__device__ __forceinline__ float rcp_approx(float x) {
    float r; asm("rcp.approx.f32 %0, %1;" : "=f"(r) : "f"(x)); return r;
}

// Horizontal 11-window: lane L holds ext elems m=4L..4L+3 (v0..v3).
// W[k] = sum over ext m'=4L+k .. m'+10.
__device__ __forceinline__ void win4(float v0, float v1, float v2, float v3,
                                     float& W0, float& W1, float& W2, float& W3)
{
    const unsigned m = 0xffffffffu;
    const float p2 = v0 + v1;
    const float p3 = p2 + v2;
    const float T  = p3 + v3;
    const float suf1 = T - v0;
    const float suf2 = v2 + v3;
    const float Tn1  = __shfl_down_sync(m, T,  1);
    const float Tn2  = __shfl_down_sync(m, T,  2);
    const float p3n2 = __shfl_down_sync(m, p3, 2);
    const float p1n3 = __shfl_down_sync(m, v0, 3);
    const float p2n3 = __shfl_down_sync(m, p2, 3);
    const float TT = Tn1 + Tn2;
    W0 = T + Tn1 + p3n2;
    W1 = suf1 + TT;
    W2 = (suf2 + p1n3) + TT;
    W3 = (v3 + p2n3) + TT;
}

#define ADMIT(k, av, bv)                                     \
    V1[k] += (av); V2[k] += (bv);                            \
    Vss[k] = fmaf((av), (av), Vss[k]);                       \
    Vss[k] = fmaf((bv), (bv), Vss[k]);                       \
    V12[k] = fmaf((av), (bv), V12[k]);

#define UPDATE(k, an, bn, ao, bo)                            \
    V1[k] += (an) - (ao); V2[k] += (bn) - (bo);              \
    Vss[k] = fmaf((an), (an), Vss[k]);                       \
    Vss[k] = fmaf((bn), (bn), Vss[k]);                       \
    Vss[k] = fmaf(-(ao), (ao), Vss[k]);                      \
    Vss[k] = fmaf(-(bo), (bo), Vss[k]);                      \
    V12[k] = fmaf((an), (bn), V12[k]);                       \
    V12[k] = fmaf(-(ao), (bo), V12[k]);

__global__ __launch_bounds__(128) void ssim_main(
    const float* __restrict__ img1, const float* __restrict__ img2,
    float* __restrict__ out)
{
    const int wib  = threadIdx.x >> 5;
    const int w    = blockIdx.x * WPB + wib;
    const int lane = threadIdx.x & 31;
    const int tid  = threadIdx.x;

    const int g     = w % NGROUPS;
    const int t     = w / NGROUPS;
    const int img   = t & 15;
    const int s     = t >> 4;                // strip index 0..36

    // Mixed strip heights: 23 strips of 14 rows, then 14 strips of 13.
    const int r0 = (s < 23) ? (14 * s) : (322 + 13 * (s - 23));
    const int H  = (s < 23) ? 14 : 13;

    // Aligned ext base; output range partition over groups.
    const int e0 = 116 * g - 8;
    const int lo = (g == 0) ? 0    : (116 * g - 3);
    const int hi = (g == 4) ? OUTW : (116 * g + 113);

    const int ec = e0 + 4 * lane;                  // lane's quad ext start
    const bool loadok = (ec >= 0) && (ec <= 500);  // whole quad in [0,504)

    bool ov[4];
    #pragma unroll
    for (int k = 0; k < 4; ++k) {
        const int c = ec + 5 + k;                  // output col of W[k]
        ov[k] = (c >= lo) && (c < hi);
    }

    // Quad pointers: global col = ec + 4 (aligned); row r at +(r+4)*W4.
    const float4* q1 = reinterpret_cast<const float4*>(
        img1 + (size_t)img * IMG_STRIDE) + ((ec >> 2) + 1);
    const float4* q2 = reinterpret_cast<const float4*>(
        img2 + (size_t)img * IMG_STRIDE) + ((ec >> 2) + 1);

    float V1[4]  = {0.f, 0.f, 0.f, 0.f};
    float V2[4]  = {0.f, 0.f, 0.f, 0.f};
    float Vss[4] = {0.f, 0.f, 0.f, 0.f};
    float V12[4] = {0.f, 0.f, 0.f, 0.f};

    // Prologue: V = rows r0-5 .. r0+5 (zero-padded below 0).
    {
        const float4* pP1 = q1 + (ptrdiff_t)(r0 - 1) * W4;   // row r0-5
        const float4* pP2 = q2 + (ptrdiff_t)(r0 - 1) * W4;
        #pragma unroll
        for (int j = 0; j < 11; ++j) {
            const int r = r0 - 5 + j;
            float4 a = {0.f,0.f,0.f,0.f}, b = {0.f,0.f,0.f,0.f};
            if (loadok && r >= 0) { a = __ldg(pP1); b = __ldg(pP2); }
            pP1 += W4; pP2 += W4;
            ADMIT(0, a.x, b.x) ADMIT(1, a.y, b.y)
            ADMIT(2, a.z, b.z) ADMIT(3, a.w, b.w)
        }
    }

    const float C1K  = 6.5025f  * 14641.f;   // C1 * 121^2
    const float C2K  = 58.5225f * 14641.f;   // C2 * 121^2
    const float C12K = C1K + C2K;
    float acc = 0.f;

    const float4* pA1 = q1 + (ptrdiff_t)(r0 + 10) * W4;  // admit row r0+6
    const float4* pA2 = q2 + (ptrdiff_t)(r0 + 10) * W4;  // (retire = -11 rows)

    #pragma unroll 2
    for (int i = 0; i < H; ++i) {
        const int y = r0 + i;

        // Issue next-state loads FIRST (consumed ~150 instrs later).
        float4 na = {0.f,0.f,0.f,0.f}, nb = {0.f,0.f,0.f,0.f};
        float4 oa = {0.f,0.f,0.f,0.f}, ob = {0.f,0.f,0.f,0.f};
        if (loadok && y <= OUTW - 7) { na = __ldg(pA1); nb = __ldg(pA2); }
        if (loadok && y >= 5) {
            oa = __ldg(pA1 - RETIRE_OFF);   // row y-5 (L1 hit, 11-row reuse)
            ob = __ldg(pA2 - RETIRE_OFF);
        }
        pA1 += W4; pA2 += W4;

        // Horizontal windows on CURRENT vertical state (no dep on loads).
        float B1[4], B2[4], Bss[4], B12[4];
        win4(V1[0],  V1[1],  V1[2],  V1[3],  B1[0],  B1[1],  B1[2],  B1[3]);
        win4(V2[0],  V2[1],  V2[2],  V2[3],  B2[0],  B2[1],  B2[2],  B2[3]);
        win4(Vss[0], Vss[1], Vss[2], Vss[3], Bss[0], Bss[1], Bss[2], Bss[3]);
        win4(V12[0], V12[1], V12[2], V12[3], B12[0], B12[1], B12[2], B12[3]);

        // SSIM in 121-scaled domain, constants folded into fma chains;
        // one reciprocal per 2 pixels.
        float nm[4], dn[4];
        #pragma unroll
        for (int k = 0; k < 4; ++k) {
            const float P    = B1[k] * B2[k];
            const float qc1  = fmaf(B1[k], B1[k],
                               fmaf(B2[k], B2[k], C1K));      // Q + C1K
            const float tden = fmaf(121.f, Bss[k], C12K - qc1); // tss + C2K
            const float n1   = fmaf(2.f, P, C1K);
            const float n2   = fmaf(242.f, B12[k], fmaf(-2.f, P, C2K));
            nm[k] = n1 * n2;
            dn[k] = qc1 * tden;
        }
        #pragma unroll
        for (int p = 0; p < 2; ++p) {
            const int k0 = 2 * p, k1 = 2 * p + 1;
            const float rr = rcp_approx(dn[k0] * dn[k1]);
            const float t0 = nm[k0] * dn[k1];
            const float t1 = nm[k1] * dn[k0];
            if (ov[k0]) acc = fmaf(t0, rr, acc);
            if (ov[k1]) acc = fmaf(t1, rr, acc);
        }

        // Apply vertical update: V(y) -> V(y+1).
        UPDATE(0, na.x, nb.x, oa.x, ob.x)
        UPDATE(1, na.y, nb.y, oa.y, ob.y)
        UPDATE(2, na.z, nb.z, oa.z, ob.z)
        UPDATE(3, na.w, nb.w, oa.w, ob.w)
    }

    // ---- block partial + fused final reduction ----
    #pragma unroll
    for (int d = 16; d; d >>= 1)
        acc += __shfl_xor_sync(0xffffffffu, acc, d);

    __shared__ float sp[WPB];
    __shared__ int   isLast;
    if (lane == 0) sp[wib] = acc;
    __syncthreads();
    if (tid == 0) {
        g_partials[blockIdx.x] = sp[0] + sp[1] + sp[2] + sp[3];
        __threadfence();
        isLast = (atomicAdd(&g_count, 1) == NBLOCKS - 1);
    }
    __syncthreads();

    if (isLast) {
        float v = 0.f;
        for (int i = tid; i < NBLOCKS; i += 128)
            v += __ldcg(&g_partials[i]);
        #pragma unroll
        for (int d = 16; d; d >>= 1)
            v += __shfl_xor_sync(0xffffffffu, v, d);
        if (lane == 0) sp[wib] = v;
        __syncthreads();
        if (tid == 0) {
            out[0] = (sp[0] + sp[1] + sp[2] + sp[3]) * (1.0f / 4064256.0f);
            g_count = 0;   // reset for next graph replay
        }
    }
}

extern "C" void kernel_launch(void* const* d_in, const int* in_sizes, int n_in,
                              void* d_out, int out_size)
{
    const float* img1 = (const float*)d_in[0];
    const float* img2 = (const float*)d_in[1];
    float* out = (float*)d_out;
    ssim_main<<<NBLOCKS, 128>>>(img1, img2, out);
}